// round 14
// baseline (speedup 1.0000x reference)
#include <cuda_runtime.h>
#include <cuda_bf16.h>

#define BATCH 32
#define SEQ   512
#define DIM   1024
#define HID   1024
#define NCTA  128
#define NTH   256

typedef unsigned long long ull;

// ---------------- scratch (device globals; no cudaMalloc allowed) ----------
__device__ float g_xu[(size_t)SEQ * BATCH * 4 * HID];   // [s][b][gate][j]
__device__ unsigned g_flags[NCTA * 8];                  // 32B-strided step counters
__device__ __nv_bfloat16 g_xh[(size_t)16384 * 1024];    // x hi  [m][k]
__device__ __nv_bfloat16 g_xl[(size_t)16384 * 1024];    // x lo
__device__ __nv_bfloat16 g_uh[(size_t)4 * 1024 * 1024]; // U hi  [g][k][n]
__device__ __nv_bfloat16 g_ul[(size_t)4 * 1024 * 1024]; // U lo
__device__ __nv_bfloat16 g_hbh[2][BATCH * HID];         // h hi [par][m][k]
__device__ __nv_bfloat16 g_hbl[2][BATCH * HID];         // h lo [par][m][k]

__device__ __forceinline__ float sigmoidf_(float x) {
    return 1.0f / (1.0f + __expf(-x));
}

// ---------------- tensor-core / async helpers --------------------------------
__device__ __forceinline__ unsigned smem_u32(const void* p) {
    return (unsigned)__cvta_generic_to_shared(p);
}
__device__ __forceinline__ void ldm_x4(unsigned* r, unsigned addr) {
    asm volatile("ldmatrix.sync.aligned.m8n8.x4.shared.b16 {%0,%1,%2,%3}, [%4];"
                 : "=r"(r[0]), "=r"(r[1]), "=r"(r[2]), "=r"(r[3]) : "r"(addr));
}
__device__ __forceinline__ void ldm_x4t(unsigned* r, unsigned addr) {
    asm volatile("ldmatrix.sync.aligned.m8n8.x4.trans.shared.b16 {%0,%1,%2,%3}, [%4];"
                 : "=r"(r[0]), "=r"(r[1]), "=r"(r[2]), "=r"(r[3]) : "r"(addr));
}
__device__ __forceinline__ void mma_bf16(float* d, const unsigned* a, const unsigned* b) {
    asm volatile(
        "mma.sync.aligned.m16n8k16.row.col.f32.bf16.bf16.f32 "
        "{%0,%1,%2,%3}, {%4,%5,%6,%7}, {%8,%9}, {%0,%1,%2,%3};"
        : "+f"(d[0]), "+f"(d[1]), "+f"(d[2]), "+f"(d[3])
        : "r"(a[0]), "r"(a[1]), "r"(a[2]), "r"(a[3]), "r"(b[0]), "r"(b[1]));
}
__device__ __forceinline__ void cp16(unsigned saddr, const void* g) {
    asm volatile("cp.async.cg.shared.global [%0], [%1], 16;" :: "r"(saddr), "l"(g));
}
__device__ __forceinline__ void cp_commit() {
    asm volatile("cp.async.commit_group;");
}
template <int N> __device__ __forceinline__ void cp_wait() {
    asm volatile("cp.async.wait_group %0;" :: "n"(N));
}

// ---------------------------------------------------------------------------
// init: g_hbh/g_hbl[0][m][k] = split(h0[m][k]); flags = 0
// ---------------------------------------------------------------------------
__global__ void init_state(const float* __restrict__ h0) {
    int idx = blockIdx.x * 256 + threadIdx.x;   // 0 .. 32767 = m*1024+k
    float v = h0[idx];
    __nv_bfloat16 hi = __float2bfloat16_rn(v);
    __nv_bfloat16 lo = __float2bfloat16_rn(v - __bfloat162float(hi));
    g_hbh[0][idx] = hi;
    g_hbl[0][idx] = lo;
    if (idx < NCTA * 8) g_flags[idx] = 0;
}

// ---------------------------------------------------------------------------
// cvt_split: fp32 -> (bf16 hi, bf16 lo) for x and the 4 gate U matrices.
// ---------------------------------------------------------------------------
#define XN4 ((size_t)16384 * 1024 / 4)
#define UG4 ((size_t)1024 * 1024 / 4)
__global__ __launch_bounds__(256) void cvt_split(
    const float* __restrict__ x,
    const float* __restrict__ Ui, const float* __restrict__ Uf,
    const float* __restrict__ Uc, const float* __restrict__ Uo)
{
    size_t i4 = (size_t)blockIdx.x * 256 + threadIdx.x;
    const float4* src;
    __nv_bfloat162* dh;
    __nv_bfloat162* dl;
    size_t off;
    if (i4 < XN4) {
        src = (const float4*)x;   off = i4;
        dh = (__nv_bfloat162*)g_xh;
        dl = (__nv_bfloat162*)g_xl;
    } else {
        size_t j = i4 - XN4;
        int g = (int)(j >> 18);               // UG4 = 2^18
        size_t o = j & (UG4 - 1);
        const float* Ug = (g == 0) ? Ui : (g == 1) ? Uf : (g == 2) ? Uc : Uo;
        src = (const float4*)Ug;  off = o;
        dh = (__nv_bfloat162*)(g_uh + (size_t)g * 1024 * 1024);
        dl = (__nv_bfloat162*)(g_ul + (size_t)g * 1024 * 1024);
    }
    float4 v = src[off];
    __nv_bfloat16 h0 = __float2bfloat16_rn(v.x);
    __nv_bfloat16 h1 = __float2bfloat16_rn(v.y);
    __nv_bfloat16 h2 = __float2bfloat16_rn(v.z);
    __nv_bfloat16 h3 = __float2bfloat16_rn(v.w);
    __nv_bfloat16 l0 = __float2bfloat16_rn(v.x - __bfloat162float(h0));
    __nv_bfloat16 l1 = __float2bfloat16_rn(v.y - __bfloat162float(h1));
    __nv_bfloat16 l2 = __float2bfloat16_rn(v.z - __bfloat162float(h2));
    __nv_bfloat16 l3 = __float2bfloat16_rn(v.w - __bfloat162float(h3));
    dh[off * 2]     = __halves2bfloat162(h0, h1);
    dh[off * 2 + 1] = __halves2bfloat162(h2, h3);
    dl[off * 2]     = __halves2bfloat162(l0, l1);
    dl[off * 2 + 1] = __halves2bfloat162(l2, l3);
}

// ---------------------------------------------------------------------------
// Phase 1: g_xu = x @ U_g + b_g, split-bf16 mma.sync, 2-stage cp.async pipe.
// (unchanged R11 winner)
// ---------------------------------------------------------------------------
#define AS_STR 40
#define BS_STR 136
#define O_ASL  (128 * AS_STR)                 // 5120
#define O_BSH  (2 * 128 * AS_STR)             // 10240
#define O_BSL  (O_BSH + 32 * BS_STR)          // 14592
#define BUF_E  (O_BSL + 32 * BS_STR)          // 18944 bf16 elems / buffer
#define XU_SMEM (2 * BUF_E * 2)               // 75776 bytes

__global__ __launch_bounds__(256, 2) void xu_mma(
    const float* __restrict__ bi, const float* __restrict__ bf,
    const float* __restrict__ bc, const float* __restrict__ bo)
{
    extern __shared__ __nv_bfloat16 smb[];

    const int tid  = threadIdx.x;
    const int wid  = tid >> 5;
    const int lane = tid & 31;
    const int wm   = wid & 3;
    const int wn   = wid >> 2;
    const int m0   = blockIdx.x * 128;
    const int nb   = blockIdx.y;
    const int gate = nb >> 3;
    const int j0   = (nb & 7) * 128;

    const float* bias = (gate == 0) ? bi : (gate == 1) ? bf : (gate == 2) ? bc : bo;
    const __nv_bfloat16* __restrict__ Agh = g_xh;
    const __nv_bfloat16* __restrict__ Agl = g_xl;
    const __nv_bfloat16* __restrict__ Bgh = g_uh + (size_t)gate * 1024 * 1024;
    const __nv_bfloat16* __restrict__ Bgl = g_ul + (size_t)gate * 1024 * 1024;

    float acc[2][8][4];
    #pragma unroll
    for (int ti = 0; ti < 2; ti++)
        #pragma unroll
        for (int tj = 0; tj < 8; tj++)
            #pragma unroll
            for (int q = 0; q < 4; q++) acc[ti][tj][q] = 0.f;

    const int ar  = tid >> 2;
    const int ac  = tid & 3;
    const int br  = tid >> 4;
    const int bc2 = tid & 15;

    const int a_r = (lane & 15);
    const int a_c = (lane >> 4) << 3;
    const int b_k = (lane & 15);
    const int b_n = (lane >> 4) << 3;

    auto stage = [&](int b, int k0) {
        __nv_bfloat16* base = smb + b * BUF_E;
        #pragma unroll
        for (int u = 0; u < 2; ++u) {
            int row = ar + u * 64;
            cp16(smem_u32(&base[row * AS_STR + ac * 8]),
                 &Agh[(size_t)(m0 + row) * DIM + k0 + ac * 8]);
            cp16(smem_u32(&base[O_ASL + row * AS_STR + ac * 8]),
                 &Agl[(size_t)(m0 + row) * DIM + k0 + ac * 8]);
            int krow = br + u * 16;
            cp16(smem_u32(&base[O_BSH + krow * BS_STR + bc2 * 8]),
                 &Bgh[(size_t)(k0 + krow) * HID + j0 + bc2 * 8]);
            cp16(smem_u32(&base[O_BSL + krow * BS_STR + bc2 * 8]),
                 &Bgl[(size_t)(k0 + krow) * HID + j0 + bc2 * 8]);
        }
    };

    stage(0, 0);
    cp_commit();

    for (int c = 0; c < 32; ++c) {
        if (c < 31) {
            stage((c + 1) & 1, (c + 1) * 32);
            cp_commit();
            cp_wait<1>();
        } else {
            cp_wait<0>();
        }
        __syncthreads();

        const __nv_bfloat16* base = smb + (c & 1) * BUF_E;
        #pragma unroll
        for (int kk = 0; kk < 32; kk += 16) {
            unsigned Ah[2][4], Al[2][4], Bf[4][4];
            #pragma unroll
            for (int ti = 0; ti < 2; ++ti) {
                int row = wm * 32 + ti * 16 + a_r;
                ldm_x4(Ah[ti], smem_u32(&base[row * AS_STR + kk + a_c]));
                ldm_x4(Al[ti], smem_u32(&base[O_ASL + row * AS_STR + kk + a_c]));
            }
            #pragma unroll
            for (int p = 0; p < 4; ++p) {
                int n = wn * 64 + p * 16 + b_n;
                ldm_x4t(Bf[p], smem_u32(&base[O_BSH + (kk + b_k) * BS_STR + n]));
            }
            #pragma unroll
            for (int ti = 0; ti < 2; ++ti)
                #pragma unroll
                for (int p = 0; p < 4; ++p) {
                    mma_bf16(acc[ti][2 * p],     Ah[ti], &Bf[p][0]);
                    mma_bf16(acc[ti][2 * p + 1], Ah[ti], &Bf[p][2]);
                    mma_bf16(acc[ti][2 * p],     Al[ti], &Bf[p][0]);
                    mma_bf16(acc[ti][2 * p + 1], Al[ti], &Bf[p][2]);
                }
            #pragma unroll
            for (int p = 0; p < 4; ++p) {
                int n = wn * 64 + p * 16 + b_n;
                ldm_x4t(Bf[p], smem_u32(&base[O_BSL + (kk + b_k) * BS_STR + n]));
            }
            #pragma unroll
            for (int ti = 0; ti < 2; ++ti)
                #pragma unroll
                for (int p = 0; p < 4; ++p) {
                    mma_bf16(acc[ti][2 * p],     Ah[ti], &Bf[p][0]);
                    mma_bf16(acc[ti][2 * p + 1], Ah[ti], &Bf[p][2]);
                }
        }
        __syncthreads();
    }

    #pragma unroll
    for (int ti = 0; ti < 2; ++ti) {
        #pragma unroll
        for (int tj = 0; tj < 8; ++tj) {
            int col = j0 + wn * 64 + tj * 8 + (lane & 3) * 2;
            float c0 = __ldg(&bias[col]);
            float c1 = __ldg(&bias[col + 1]);
            int row0 = m0 + wm * 32 + ti * 16 + (lane >> 2);
            int row1 = row0 + 8;
            {
                int b_ = row0 >> 9, s_ = row0 & 511;
                float2* dst = (float2*)&g_xu[(((size_t)s_ * BATCH + b_) * 4 + gate) * HID + col];
                *dst = make_float2(acc[ti][tj][0] + c0, acc[ti][tj][1] + c1);
            }
            {
                int b_ = row1 >> 9, s_ = row1 & 511;
                float2* dst = (float2*)&g_xu[(((size_t)s_ * BATCH + b_) * 4 + gate) * HID + col];
                *dst = make_float2(acc[ti][tj][2] + c0, acc[ti][tj][3] + c1);
            }
        }
    }
}

// ---------------------------------------------------------------------------
// Phase 2: PERSISTENT recurrence — R11 skeleton (256 threads, upfront
// distributed flag wait, single Hs buffer, 2 syncs/chunk) with a 4-k x 2-m
// warp mapping: warp (ks = wid&3, ms = wid>>2) does m-rows [ms*16,+16) over
// k-slice [ks*64,+64) per chunk. Reduction fan-in 4 (was 8).
// ---------------------------------------------------------------------------
#define VB_STR 40     // V smem row stride (bf16) — multiple of 8 (ldmatrix 16B)
#define HB_STR 264    // H smem row stride (bf16)
#define SC_SSTR (32 * 36)   // scratch floats per k-slot (4 slots)
#define SMEM_BYTES (2 * 1024 * VB_STR * 2 + 8 * SC_SSTR * 4)   // 163840+36864

__global__ __launch_bounds__(NTH, 1) void lstm_persist(
    const float* __restrict__ Vi, const float* __restrict__ Vf,
    const float* __restrict__ Vc, const float* __restrict__ Vo,
    const float* __restrict__ c0,
    float* __restrict__ out_hs,
    float* __restrict__ out_ht,
    float* __restrict__ out_ct)
{
    extern __shared__ char smraw[];
    __nv_bfloat16* Vbh = (__nv_bfloat16*)smraw;            // [1024][VB_STR]
    __nv_bfloat16* Vbl = Vbh + 1024 * VB_STR;
    char* hregion = smraw + (size_t)2 * 1024 * VB_STR * 2;
    __nv_bfloat16* Hsh = (__nv_bfloat16*)hregion;          // [32][HB_STR]
    __nv_bfloat16* Hsl = Hsh + 32 * HB_STR;
    float* scr = (float*)hregion;                          // [4][32][36] alias

    const int tid  = threadIdx.x;
    const int wid  = tid >> 5;
    const int lane = tid & 31;
    const int ks   = wid & 3;            // k-split slot 0..3
    const int ms   = wid >> 2;           // m-half 0..1
    const int jb   = blockIdx.x * 8;

    const int fm  = tid >> 3;            // gating: batch
    const int fj  = tid & 7;             // gating: local column
    const int fjg = jb + fj;

    const int a_r = (lane & 15);
    const int a_c = (lane >> 4) << 3;
    const int b_k = (lane & 15);
    const int b_n = (lane >> 4) << 3;

    // producer flags this thread depends on: chunk ch slice kq -> CTA ch*32+kq
    const int kq5 = tid & 31;
    const unsigned* fl0 = &g_flags[(0 * 32 + kq5) * 8];
    const unsigned* fl1 = &g_flags[(1 * 32 + kq5) * 8];
    const unsigned* fl2 = &g_flags[(2 * 32 + kq5) * 8];
    const unsigned* fl3 = &g_flags[(3 * 32 + kq5) * 8];

    // ---- one-time V load + split into smem ----
    for (int e = tid; e < 1024 * 32; e += NTH) {
        int k   = e >> 5;
        int col = e & 31;
        int j   = col >> 2;
        int g   = col & 3;
        const float* Vg = (g == 0) ? Vi : (g == 1) ? Vf : (g == 2) ? Vc : Vo;
        float v = __ldg(&Vg[(size_t)k * HID + jb + j]);
        __nv_bfloat16 hi = __float2bfloat16_rn(v);
        __nv_bfloat16 lo = __float2bfloat16_rn(v - __bfloat162float(hi));
        Vbh[k * VB_STR + col] = hi;
        Vbl[k * VB_STR + col] = lo;
    }
    float cc = __ldg(&c0[fm * HID + fjg]);
    __syncthreads();

    for (int s = 0; s < SEQ; ++s) {
        const __nv_bfloat16* __restrict__ hH = g_hbh[s & 1];
        const __nv_bfloat16* __restrict__ hL = g_hbl[s & 1];

        const float* xup = &g_xu[(((size_t)s * BATCH + fm) * 4) * HID + fjg];
        float xi = __ldcs(xup);
        float xf = __ldcs(xup + HID);
        float xg = __ldcs(xup + 2 * HID);
        float xo = __ldcs(xup + 3 * HID);

        // ---- distributed wait: only this thread's 4 producers ----
        {
            unsigned tgt = (unsigned)s;
            unsigned v0, v1, v2, v3;
            do {
                asm volatile("ld.acquire.gpu.global.u32 %0, [%1];" : "=r"(v0) : "l"(fl0));
                asm volatile("ld.acquire.gpu.global.u32 %0, [%1];" : "=r"(v1) : "l"(fl1));
                asm volatile("ld.acquire.gpu.global.u32 %0, [%1];" : "=r"(v2) : "l"(fl2));
                asm volatile("ld.acquire.gpu.global.u32 %0, [%1];" : "=r"(v3) : "l"(fl3));
            } while (v0 < tgt || v1 < tgt || v2 < tgt || v3 < tgt);
        }

        float acc[4][4];     // [n-tile of 8][frag]
        #pragma unroll
        for (int nj = 0; nj < 4; nj++)
            #pragma unroll
            for (int q = 0; q < 4; q++) acc[nj][q] = 0.f;

        // prefetch chunk 0: [32 m][256 k] hi+lo (uint4 = 8 bf16)
        uint4 hrH[4], hrL[4];
        #pragma unroll
        for (int r = 0; r < 4; ++r) {
            int idx = r * 256 + tid;      // 0..1023
            int m   = idx >> 5;
            int kq  = idx & 31;
            hrH[r] = __ldcg((const uint4*)&hH[m * HID + kq * 8]);
            hrL[r] = __ldcg((const uint4*)&hL[m * HID + kq * 8]);
        }

        #pragma unroll
        for (int ch = 0; ch < 4; ++ch) {
            __syncthreads();              // previous chunk compute / scratch done
            #pragma unroll
            for (int r = 0; r < 4; ++r) {
                int idx = r * 256 + tid;
                int m   = idx >> 5;
                int kq  = idx & 31;
                *(uint4*)&Hsh[m * HB_STR + kq * 8] = hrH[r];
                *(uint4*)&Hsl[m * HB_STR + kq * 8] = hrL[r];
            }
            __syncthreads();
            if (ch < 3) {
                #pragma unroll
                for (int r = 0; r < 4; ++r) {
                    int idx = r * 256 + tid;
                    int m   = idx >> 5;
                    int kq  = idx & 31;
                    hrH[r] = __ldcg((const uint4*)&hH[m * HID + (ch + 1) * 256 + kq * 8]);
                    hrL[r] = __ldcg((const uint4*)&hL[m * HID + (ch + 1) * 256 + kq * 8]);
                }
            }

            // warp's slice: m-rows [ms*16,+16), k [ks*64, ks*64+64) of chunk
            #pragma unroll
            for (int kk = 0; kk < 64; kk += 16) {
                int kloc = ks * 64 + kk;              // k within chunk
                int kglb = ch * 256 + kloc;           // k within 1024 (for V)
                unsigned Ah[4], Al[4], Bh[2][4], Bl[2][4];
                {
                    int row = ms * 16 + a_r;
                    ldm_x4(Ah, smem_u32(&Hsh[row * HB_STR + kloc + a_c]));
                    ldm_x4(Al, smem_u32(&Hsl[row * HB_STR + kloc + a_c]));
                }
                #pragma unroll
                for (int q = 0; q < 2; ++q) {
                    int n = q * 16 + b_n;
                    ldm_x4t(Bh[q], smem_u32(&Vbh[(kglb + b_k) * VB_STR + n]));
                    ldm_x4t(Bl[q], smem_u32(&Vbl[(kglb + b_k) * VB_STR + n]));
                }
                #pragma unroll
                for (int q = 0; q < 2; ++q) {
                    mma_bf16(acc[2 * q],     Ah, &Bh[q][0]);
                    mma_bf16(acc[2 * q + 1], Ah, &Bh[q][2]);
                    mma_bf16(acc[2 * q],     Al, &Bh[q][0]);
                    mma_bf16(acc[2 * q + 1], Al, &Bh[q][2]);
                    mma_bf16(acc[2 * q],     Ah, &Bl[q][0]);
                    mma_bf16(acc[2 * q + 1], Ah, &Bl[q][2]);
                }
            }
        }

        // ---- cross-warp reduction via scratch (4 k-slots; warp writes its
        //      own 16 m-rows) ----
        __syncthreads();
        #pragma unroll
        for (int nj = 0; nj < 4; ++nj)
            #pragma unroll
            for (int u = 0; u < 2; ++u) {
                int row = ms * 16 + (lane >> 2) + u * 8;
                int col = nj * 8 + (lane & 3) * 2;
                *(float2*)&scr[ks * SC_SSTR + row * 36 + col] =
                    make_float2(acc[nj][2 * u], acc[nj][2 * u + 1]);
            }
        __syncthreads();

        float zi = xi, zf = xf, zg = xg, zo = xo;
        #pragma unroll
        for (int w4 = 0; w4 < 4; ++w4) {
            float4 p = *(const float4*)&scr[w4 * SC_SSTR + fm * 36 + fj * 4];
            zi += p.x; zf += p.y; zg += p.z; zo += p.w;
        }

        float ig = sigmoidf_(zi);
        float fg = sigmoidf_(zf);
        float gg = tanhf(zg);
        float og = sigmoidf_(zo);
        cc = fg * cc + ig * gg;
        float h = og * tanhf(cc);

        __nv_bfloat16 hhi = __float2bfloat16_rn(h);
        __nv_bfloat16 hlo = __float2bfloat16_rn(h - __bfloat162float(hhi));
        g_hbh[(s + 1) & 1][fm * HID + fjg] = hhi;
        g_hbl[(s + 1) & 1][fm * HID + fjg] = hlo;

        __syncthreads();                  // all h stores + scratch reads done
        if (tid == 0) {
            asm volatile("st.release.gpu.global.u32 [%0], %1;"
                         :: "l"(&g_flags[blockIdx.x * 8]), "r"((unsigned)(s + 1))
                         : "memory");
        }

        // streaming output store AFTER the flag post (off the critical path)
        __stcs(&out_hs[((size_t)fm * SEQ + s) * HID + fjg], h);

        if (s == SEQ - 1) {
            out_ht[fm * HID + fjg] = h;
            out_ct[fm * HID + fjg] = cc;
        }
    }
}

// ---------------------------------------------------------------------------
extern "C" void kernel_launch(void* const* d_in, const int* in_sizes, int n_in,
                              void* d_out, int out_size) {
    const float* x   = (const float*)d_in[0];
    const float* h0  = (const float*)d_in[1];
    const float* c0  = (const float*)d_in[2];
    const float* U_i = (const float*)d_in[3];
    const float* V_i = (const float*)d_in[4];
    const float* b_i = (const float*)d_in[5];
    const float* U_f = (const float*)d_in[6];
    const float* V_f = (const float*)d_in[7];
    const float* b_f = (const float*)d_in[8];
    const float* U_c = (const float*)d_in[9];
    const float* V_c = (const float*)d_in[10];
    const float* b_c = (const float*)d_in[11];
    const float* U_o = (const float*)d_in[12];
    const float* V_o = (const float*)d_in[13];
    const float* b_o = (const float*)d_in[14];

    float* out    = (float*)d_out;
    float* out_hs = out;
    float* out_ht = out + (size_t)BATCH * SEQ * HID;
    float* out_ct = out_ht + (size_t)BATCH * HID;

    static_assert(SMEM_BYTES <= 232448, "smem budget (persist)");
    static_assert(XU_SMEM <= 101376, "smem budget (xu, 2/SM)");
    cudaFuncSetAttribute(lstm_persist,
                         cudaFuncAttributeMaxDynamicSharedMemorySize,
                         SMEM_BYTES);
    cudaFuncSetAttribute(xu_mma,
                         cudaFuncAttributeMaxDynamicSharedMemorySize,
                         XU_SMEM);

    init_state<<<128, 256>>>(h0);

    size_t total4 = XN4 + 4 * UG4;
    cvt_split<<<(unsigned)(total4 / 256), 256>>>(x, U_i, U_f, U_c, U_o);

    dim3 g1(128, 32);
    xu_mma<<<g1, 256, XU_SMEM>>>(b_i, b_f, b_c, b_o);

    lstm_persist<<<NCTA, NTH, SMEM_BYTES>>>(
        V_i, V_f, V_c, V_o, c0, out_hs, out_ht, out_ct);
}

// round 15
// speedup vs baseline: 1.0847x; 1.0847x over previous
#include <cuda_runtime.h>
#include <cuda_bf16.h>

#define BATCH 32
#define SEQ   512
#define DIM   1024
#define HID   1024
#define NCTA  128
#define NTH   256

typedef unsigned long long ull;

// ---------------- scratch (device globals; no cudaMalloc allowed) ----------
__device__ float g_xu[(size_t)SEQ * BATCH * 4 * HID];   // [s][b][gate][j]
__device__ unsigned g_flags[NCTA * 8];                  // 32B-strided step counters
__device__ __nv_bfloat16 g_xh[(size_t)16384 * 1024];    // x hi  [m][k]
__device__ __nv_bfloat16 g_xl[(size_t)16384 * 1024];    // x lo
__device__ __nv_bfloat16 g_uh[(size_t)4 * 1024 * 1024]; // U hi  [g][k][n]
__device__ __nv_bfloat16 g_ul[(size_t)4 * 1024 * 1024]; // U lo
__device__ __nv_bfloat16 g_hbh[2][BATCH * HID];         // h hi [par][m][k]
__device__ __nv_bfloat16 g_hbl[2][BATCH * HID];         // h lo [par][m][k]

__device__ __forceinline__ float sigmoidf_(float x) {
    return 1.0f / (1.0f + __expf(-x));
}

// ---------------- tensor-core / async helpers --------------------------------
__device__ __forceinline__ unsigned smem_u32(const void* p) {
    return (unsigned)__cvta_generic_to_shared(p);
}
__device__ __forceinline__ void ldm_x4(unsigned* r, unsigned addr) {
    asm volatile("ldmatrix.sync.aligned.m8n8.x4.shared.b16 {%0,%1,%2,%3}, [%4];"
                 : "=r"(r[0]), "=r"(r[1]), "=r"(r[2]), "=r"(r[3]) : "r"(addr));
}
__device__ __forceinline__ void ldm_x4t(unsigned* r, unsigned addr) {
    asm volatile("ldmatrix.sync.aligned.m8n8.x4.trans.shared.b16 {%0,%1,%2,%3}, [%4];"
                 : "=r"(r[0]), "=r"(r[1]), "=r"(r[2]), "=r"(r[3]) : "r"(addr));
}
__device__ __forceinline__ void mma_bf16(float* d, const unsigned* a, const unsigned* b) {
    asm volatile(
        "mma.sync.aligned.m16n8k16.row.col.f32.bf16.bf16.f32 "
        "{%0,%1,%2,%3}, {%4,%5,%6,%7}, {%8,%9}, {%0,%1,%2,%3};"
        : "+f"(d[0]), "+f"(d[1]), "+f"(d[2]), "+f"(d[3])
        : "r"(a[0]), "r"(a[1]), "r"(a[2]), "r"(a[3]), "r"(b[0]), "r"(b[1]));
}
__device__ __forceinline__ void cp16(unsigned saddr, const void* g) {
    asm volatile("cp.async.cg.shared.global [%0], [%1], 16;" :: "r"(saddr), "l"(g));
}
__device__ __forceinline__ void cp_commit() {
    asm volatile("cp.async.commit_group;");
}
template <int N> __device__ __forceinline__ void cp_wait() {
    asm volatile("cp.async.wait_group %0;" :: "n"(N));
}

// ---------------------------------------------------------------------------
// cvt_split: fp32 -> (bf16 hi, bf16 lo) for x and the 4 gate U matrices.
// Block 0 additionally seeds g_hbh/g_hbl[0] from h0 and zeroes the flags.
// ---------------------------------------------------------------------------
#define XN4 ((size_t)16384 * 1024 / 4)
#define UG4 ((size_t)1024 * 1024 / 4)
__global__ __launch_bounds__(256) void cvt_split(
    const float* __restrict__ x,  const float* __restrict__ h0,
    const float* __restrict__ Ui, const float* __restrict__ Uf,
    const float* __restrict__ Uc, const float* __restrict__ Uo)
{
    if (blockIdx.x == 0) {
        for (int idx = threadIdx.x; idx < BATCH * HID; idx += 256) {
            float v = h0[idx];
            __nv_bfloat16 hi = __float2bfloat16_rn(v);
            __nv_bfloat16 lo = __float2bfloat16_rn(v - __bfloat162float(hi));
            g_hbh[0][idx] = hi;
            g_hbl[0][idx] = lo;
        }
        for (int e = threadIdx.x; e < NCTA * 8; e += 256) g_flags[e] = 0;
    }

    size_t i4 = (size_t)blockIdx.x * 256 + threadIdx.x;
    const float4* src;
    __nv_bfloat162* dh;
    __nv_bfloat162* dl;
    size_t off;
    if (i4 < XN4) {
        src = (const float4*)x;   off = i4;
        dh = (__nv_bfloat162*)g_xh;
        dl = (__nv_bfloat162*)g_xl;
    } else {
        size_t j = i4 - XN4;
        int g = (int)(j >> 18);               // UG4 = 2^18
        size_t o = j & (UG4 - 1);
        const float* Ug = (g == 0) ? Ui : (g == 1) ? Uf : (g == 2) ? Uc : Uo;
        src = (const float4*)Ug;  off = o;
        dh = (__nv_bfloat162*)(g_uh + (size_t)g * 1024 * 1024);
        dl = (__nv_bfloat162*)(g_ul + (size_t)g * 1024 * 1024);
    }
    float4 v = src[off];
    __nv_bfloat16 h0v = __float2bfloat16_rn(v.x);
    __nv_bfloat16 h1 = __float2bfloat16_rn(v.y);
    __nv_bfloat16 h2 = __float2bfloat16_rn(v.z);
    __nv_bfloat16 h3 = __float2bfloat16_rn(v.w);
    __nv_bfloat16 l0 = __float2bfloat16_rn(v.x - __bfloat162float(h0v));
    __nv_bfloat16 l1 = __float2bfloat16_rn(v.y - __bfloat162float(h1));
    __nv_bfloat16 l2 = __float2bfloat16_rn(v.z - __bfloat162float(h2));
    __nv_bfloat16 l3 = __float2bfloat16_rn(v.w - __bfloat162float(h3));
    dh[off * 2]     = __halves2bfloat162(h0v, h1);
    dh[off * 2 + 1] = __halves2bfloat162(h2, h3);
    dl[off * 2]     = __halves2bfloat162(l0, l1);
    dl[off * 2 + 1] = __halves2bfloat162(l2, l3);
}

// ---------------------------------------------------------------------------
// Phase 1: g_xu = x @ U_g + b_g, split-bf16 mma.sync, 2-stage cp.async pipe.
// (unchanged R11 winner)
// ---------------------------------------------------------------------------
#define AS_STR 40
#define BS_STR 136
#define O_ASL  (128 * AS_STR)                 // 5120
#define O_BSH  (2 * 128 * AS_STR)             // 10240
#define O_BSL  (O_BSH + 32 * BS_STR)          // 14592
#define BUF_E  (O_BSL + 32 * BS_STR)          // 18944 bf16 elems / buffer
#define XU_SMEM (2 * BUF_E * 2)               // 75776 bytes

__global__ __launch_bounds__(256, 2) void xu_mma(
    const float* __restrict__ bi, const float* __restrict__ bf,
    const float* __restrict__ bc, const float* __restrict__ bo)
{
    extern __shared__ __nv_bfloat16 smb[];

    const int tid  = threadIdx.x;
    const int wid  = tid >> 5;
    const int lane = tid & 31;
    const int wm   = wid & 3;
    const int wn   = wid >> 2;
    const int m0   = blockIdx.x * 128;
    const int nb   = blockIdx.y;
    const int gate = nb >> 3;
    const int j0   = (nb & 7) * 128;

    const float* bias = (gate == 0) ? bi : (gate == 1) ? bf : (gate == 2) ? bc : bo;
    const __nv_bfloat16* __restrict__ Agh = g_xh;
    const __nv_bfloat16* __restrict__ Agl = g_xl;
    const __nv_bfloat16* __restrict__ Bgh = g_uh + (size_t)gate * 1024 * 1024;
    const __nv_bfloat16* __restrict__ Bgl = g_ul + (size_t)gate * 1024 * 1024;

    float acc[2][8][4];
    #pragma unroll
    for (int ti = 0; ti < 2; ti++)
        #pragma unroll
        for (int tj = 0; tj < 8; tj++)
            #pragma unroll
            for (int q = 0; q < 4; q++) acc[ti][tj][q] = 0.f;

    const int ar  = tid >> 2;
    const int ac  = tid & 3;
    const int br  = tid >> 4;
    const int bc2 = tid & 15;

    const int a_r = (lane & 15);
    const int a_c = (lane >> 4) << 3;
    const int b_k = (lane & 15);
    const int b_n = (lane >> 4) << 3;

    auto stage = [&](int b, int k0) {
        __nv_bfloat16* base = smb + b * BUF_E;
        #pragma unroll
        for (int u = 0; u < 2; ++u) {
            int row = ar + u * 64;
            cp16(smem_u32(&base[row * AS_STR + ac * 8]),
                 &Agh[(size_t)(m0 + row) * DIM + k0 + ac * 8]);
            cp16(smem_u32(&base[O_ASL + row * AS_STR + ac * 8]),
                 &Agl[(size_t)(m0 + row) * DIM + k0 + ac * 8]);
            int krow = br + u * 16;
            cp16(smem_u32(&base[O_BSH + krow * BS_STR + bc2 * 8]),
                 &Bgh[(size_t)(k0 + krow) * HID + j0 + bc2 * 8]);
            cp16(smem_u32(&base[O_BSL + krow * BS_STR + bc2 * 8]),
                 &Bgl[(size_t)(k0 + krow) * HID + j0 + bc2 * 8]);
        }
    };

    stage(0, 0);
    cp_commit();

    for (int c = 0; c < 32; ++c) {
        if (c < 31) {
            stage((c + 1) & 1, (c + 1) * 32);
            cp_commit();
            cp_wait<1>();
        } else {
            cp_wait<0>();
        }
        __syncthreads();

        const __nv_bfloat16* base = smb + (c & 1) * BUF_E;
        #pragma unroll
        for (int kk = 0; kk < 32; kk += 16) {
            unsigned Ah[2][4], Al[2][4], Bf[4][4];
            #pragma unroll
            for (int ti = 0; ti < 2; ++ti) {
                int row = wm * 32 + ti * 16 + a_r;
                ldm_x4(Ah[ti], smem_u32(&base[row * AS_STR + kk + a_c]));
                ldm_x4(Al[ti], smem_u32(&base[O_ASL + row * AS_STR + kk + a_c]));
            }
            #pragma unroll
            for (int p = 0; p < 4; ++p) {
                int n = wn * 64 + p * 16 + b_n;
                ldm_x4t(Bf[p], smem_u32(&base[O_BSH + (kk + b_k) * BS_STR + n]));
            }
            #pragma unroll
            for (int ti = 0; ti < 2; ++ti)
                #pragma unroll
                for (int p = 0; p < 4; ++p) {
                    mma_bf16(acc[ti][2 * p],     Ah[ti], &Bf[p][0]);
                    mma_bf16(acc[ti][2 * p + 1], Ah[ti], &Bf[p][2]);
                    mma_bf16(acc[ti][2 * p],     Al[ti], &Bf[p][0]);
                    mma_bf16(acc[ti][2 * p + 1], Al[ti], &Bf[p][2]);
                }
            #pragma unroll
            for (int p = 0; p < 4; ++p) {
                int n = wn * 64 + p * 16 + b_n;
                ldm_x4t(Bf[p], smem_u32(&base[O_BSL + (kk + b_k) * BS_STR + n]));
            }
            #pragma unroll
            for (int ti = 0; ti < 2; ++ti)
                #pragma unroll
                for (int p = 0; p < 4; ++p) {
                    mma_bf16(acc[ti][2 * p],     Ah[ti], &Bf[p][0]);
                    mma_bf16(acc[ti][2 * p + 1], Ah[ti], &Bf[p][2]);
                }
        }
        __syncthreads();
    }

    #pragma unroll
    for (int ti = 0; ti < 2; ++ti) {
        #pragma unroll
        for (int tj = 0; tj < 8; ++tj) {
            int col = j0 + wn * 64 + tj * 8 + (lane & 3) * 2;
            float c0 = __ldg(&bias[col]);
            float c1 = __ldg(&bias[col + 1]);
            int row0 = m0 + wm * 32 + ti * 16 + (lane >> 2);
            int row1 = row0 + 8;
            {
                int b_ = row0 >> 9, s_ = row0 & 511;
                float2* dst = (float2*)&g_xu[(((size_t)s_ * BATCH + b_) * 4 + gate) * HID + col];
                *dst = make_float2(acc[ti][tj][0] + c0, acc[ti][tj][1] + c1);
            }
            {
                int b_ = row1 >> 9, s_ = row1 & 511;
                float2* dst = (float2*)&g_xu[(((size_t)s_ * BATCH + b_) * 4 + gate) * HID + col];
                *dst = make_float2(acc[ti][tj][2] + c0, acc[ti][tj][3] + c1);
            }
        }
    }
}

// ---------------------------------------------------------------------------
// Phase 2: PERSISTENT recurrence — EXACT R11 winner (256 threads, 8-way
// k-split warps, single Hs buffer, 2 syncs/chunk, upfront distributed
// 4-flag wait, flag post before output store). DO NOT PERTURB: R10/R12/
// R13/R14 each modified one aspect of this skeleton and all regressed.
// ---------------------------------------------------------------------------
#define VB_STR 40     // V smem row stride (bf16) — multiple of 8 (ldmatrix 16B)
#define HB_STR 264    // H smem row stride (bf16)
#define SC_WSTR (32 * 36)   // scratch floats per warp
#define SMEM_BYTES (2 * 1024 * VB_STR * 2 + 8 * SC_WSTR * 4)   // 163840+36864

__global__ __launch_bounds__(NTH, 1) void lstm_persist(
    const float* __restrict__ Vi, const float* __restrict__ Vf,
    const float* __restrict__ Vc, const float* __restrict__ Vo,
    const float* __restrict__ c0,
    float* __restrict__ out_hs,
    float* __restrict__ out_ht,
    float* __restrict__ out_ct)
{
    extern __shared__ char smraw[];
    __nv_bfloat16* Vbh = (__nv_bfloat16*)smraw;            // [1024][VB_STR]
    __nv_bfloat16* Vbl = Vbh + 1024 * VB_STR;
    char* hregion = smraw + (size_t)2 * 1024 * VB_STR * 2;
    __nv_bfloat16* Hsh = (__nv_bfloat16*)hregion;          // [32][HB_STR]
    __nv_bfloat16* Hsl = Hsh + 32 * HB_STR;
    float* scr = (float*)hregion;                          // [8][32][36] alias

    const int tid  = threadIdx.x;
    const int wid  = tid >> 5;
    const int lane = tid & 31;
    const int jb   = blockIdx.x * 8;

    const int fm  = tid >> 3;            // gating: batch
    const int fj  = tid & 7;             // gating: local column
    const int fjg = jb + fj;

    const int a_r = (lane & 15);
    const int a_c = (lane >> 4) << 3;
    const int b_k = (lane & 15);
    const int b_n = (lane >> 4) << 3;

    // producer flags this thread depends on: chunk ch slice kq -> CTA ch*32+kq
    const int kq5 = tid & 31;
    const unsigned* fl0 = &g_flags[(0 * 32 + kq5) * 8];
    const unsigned* fl1 = &g_flags[(1 * 32 + kq5) * 8];
    const unsigned* fl2 = &g_flags[(2 * 32 + kq5) * 8];
    const unsigned* fl3 = &g_flags[(3 * 32 + kq5) * 8];

    // ---- one-time V load + split into smem ----
    for (int e = tid; e < 1024 * 32; e += NTH) {
        int k   = e >> 5;
        int col = e & 31;
        int j   = col >> 2;
        int g   = col & 3;
        const float* Vg = (g == 0) ? Vi : (g == 1) ? Vf : (g == 2) ? Vc : Vo;
        float v = __ldg(&Vg[(size_t)k * HID + jb + j]);
        __nv_bfloat16 hi = __float2bfloat16_rn(v);
        __nv_bfloat16 lo = __float2bfloat16_rn(v - __bfloat162float(hi));
        Vbh[k * VB_STR + col] = hi;
        Vbl[k * VB_STR + col] = lo;
    }
    float cc = __ldg(&c0[fm * HID + fjg]);
    __syncthreads();

    for (int s = 0; s < SEQ; ++s) {
        const __nv_bfloat16* __restrict__ hH = g_hbh[s & 1];
        const __nv_bfloat16* __restrict__ hL = g_hbl[s & 1];

        const float* xup = &g_xu[(((size_t)s * BATCH + fm) * 4) * HID + fjg];
        float xi = __ldcs(xup);
        float xf = __ldcs(xup + HID);
        float xg = __ldcs(xup + 2 * HID);
        float xo = __ldcs(xup + 3 * HID);

        // ---- distributed wait: only this thread's 4 producers ----
        {
            unsigned tgt = (unsigned)s;
            unsigned v0, v1, v2, v3;
            do {
                asm volatile("ld.acquire.gpu.global.u32 %0, [%1];" : "=r"(v0) : "l"(fl0));
                asm volatile("ld.acquire.gpu.global.u32 %0, [%1];" : "=r"(v1) : "l"(fl1));
                asm volatile("ld.acquire.gpu.global.u32 %0, [%1];" : "=r"(v2) : "l"(fl2));
                asm volatile("ld.acquire.gpu.global.u32 %0, [%1];" : "=r"(v3) : "l"(fl3));
            } while (v0 < tgt || v1 < tgt || v2 < tgt || v3 < tgt);
        }

        float acc[2][4][4];
        #pragma unroll
        for (int ti = 0; ti < 2; ti++)
            #pragma unroll
            for (int nj = 0; nj < 4; nj++)
                #pragma unroll
                for (int q = 0; q < 4; q++) acc[ti][nj][q] = 0.f;

        // prefetch chunk 0: [32 m][256 k] hi+lo (uint4 = 8 bf16)
        uint4 hrH[4], hrL[4];
        #pragma unroll
        for (int r = 0; r < 4; ++r) {
            int idx = r * 256 + tid;      // 0..1023
            int m   = idx >> 5;
            int kq  = idx & 31;
            hrH[r] = __ldcg((const uint4*)&hH[m * HID + kq * 8]);
            hrL[r] = __ldcg((const uint4*)&hL[m * HID + kq * 8]);
        }

        #pragma unroll
        for (int ch = 0; ch < 4; ++ch) {
            __syncthreads();              // previous chunk compute / scratch done
            #pragma unroll
            for (int r = 0; r < 4; ++r) {
                int idx = r * 256 + tid;
                int m   = idx >> 5;
                int kq  = idx & 31;
                *(uint4*)&Hsh[m * HB_STR + kq * 8] = hrH[r];
                *(uint4*)&Hsl[m * HB_STR + kq * 8] = hrL[r];
            }
            __syncthreads();
            if (ch < 3) {
                #pragma unroll
                for (int r = 0; r < 4; ++r) {
                    int idx = r * 256 + tid;
                    int m   = idx >> 5;
                    int kq  = idx & 31;
                    hrH[r] = __ldcg((const uint4*)&hH[m * HID + (ch + 1) * 256 + kq * 8]);
                    hrL[r] = __ldcg((const uint4*)&hL[m * HID + (ch + 1) * 256 + kq * 8]);
                }
            }

            // warp's k-slice within chunk: [wid*32, wid*32+32)
            #pragma unroll
            for (int kk = 0; kk < 32; kk += 16) {
                int kloc = wid * 32 + kk;             // k within chunk
                int kglb = ch * 256 + kloc;           // k within 1024 (for V)
                unsigned Ah[2][4], Al[2][4], Bh[2][4], Bl[2][4];
                #pragma unroll
                for (int ti = 0; ti < 2; ++ti) {
                    int row = ti * 16 + a_r;
                    ldm_x4(Ah[ti], smem_u32(&Hsh[row * HB_STR + kloc + a_c]));
                    ldm_x4(Al[ti], smem_u32(&Hsl[row * HB_STR + kloc + a_c]));
                }
                #pragma unroll
                for (int q = 0; q < 2; ++q) {
                    int n = q * 16 + b_n;
                    ldm_x4t(Bh[q], smem_u32(&Vbh[(kglb + b_k) * VB_STR + n]));
                    ldm_x4t(Bl[q], smem_u32(&Vbl[(kglb + b_k) * VB_STR + n]));
                }
                #pragma unroll
                for (int ti = 0; ti < 2; ++ti)
                    #pragma unroll
                    for (int q = 0; q < 2; ++q) {
                        mma_bf16(acc[ti][2 * q],     Ah[ti], &Bh[q][0]);
                        mma_bf16(acc[ti][2 * q + 1], Ah[ti], &Bh[q][2]);
                        mma_bf16(acc[ti][2 * q],     Al[ti], &Bh[q][0]);
                        mma_bf16(acc[ti][2 * q + 1], Al[ti], &Bh[q][2]);
                        mma_bf16(acc[ti][2 * q],     Ah[ti], &Bl[q][0]);
                        mma_bf16(acc[ti][2 * q + 1], Ah[ti], &Bl[q][2]);
                    }
            }
        }

        // ---- cross-warp reduction via scratch (aliases H region) ----
        __syncthreads();
        #pragma unroll
        for (int ti = 0; ti < 2; ++ti)
            #pragma unroll
            for (int nj = 0; nj < 4; ++nj)
                #pragma unroll
                for (int u = 0; u < 2; ++u) {
                    int row = ti * 16 + (lane >> 2) + u * 8;
                    int col = nj * 8 + (lane & 3) * 2;
                    *(float2*)&scr[wid * SC_WSTR + row * 36 + col] =
                        make_float2(acc[ti][nj][2 * u], acc[ti][nj][2 * u + 1]);
                }
        __syncthreads();

        float zi = xi, zf = xf, zg = xg, zo = xo;
        #pragma unroll
        for (int w8 = 0; w8 < 8; ++w8) {
            float4 p = *(const float4*)&scr[w8 * SC_WSTR + fm * 36 + fj * 4];
            zi += p.x; zf += p.y; zg += p.z; zo += p.w;
        }

        float ig = sigmoidf_(zi);
        float fg = sigmoidf_(zf);
        float gg = tanhf(zg);
        float og = sigmoidf_(zo);
        cc = fg * cc + ig * gg;
        float h = og * tanhf(cc);

        __nv_bfloat16 hhi = __float2bfloat16_rn(h);
        __nv_bfloat16 hlo = __float2bfloat16_rn(h - __bfloat162float(hhi));
        g_hbh[(s + 1) & 1][fm * HID + fjg] = hhi;
        g_hbl[(s + 1) & 1][fm * HID + fjg] = hlo;

        __syncthreads();                  // all h stores issued (CTA-wide)
        if (tid == 0) {
            asm volatile("st.release.gpu.global.u32 [%0], %1;"
                         :: "l"(&g_flags[blockIdx.x * 8]), "r"((unsigned)(s + 1))
                         : "memory");
        }

        // streaming output store AFTER the flag post (off the critical path)
        __stcs(&out_hs[((size_t)fm * SEQ + s) * HID + fjg], h);

        if (s == SEQ - 1) {
            out_ht[fm * HID + fjg] = h;
            out_ct[fm * HID + fjg] = cc;
        }
    }
}

// ---------------------------------------------------------------------------
extern "C" void kernel_launch(void* const* d_in, const int* in_sizes, int n_in,
                              void* d_out, int out_size) {
    const float* x   = (const float*)d_in[0];
    const float* h0  = (const float*)d_in[1];
    const float* c0  = (const float*)d_in[2];
    const float* U_i = (const float*)d_in[3];
    const float* V_i = (const float*)d_in[4];
    const float* b_i = (const float*)d_in[5];
    const float* U_f = (const float*)d_in[6];
    const float* V_f = (const float*)d_in[7];
    const float* b_f = (const float*)d_in[8];
    const float* U_c = (const float*)d_in[9];
    const float* V_c = (const float*)d_in[10];
    const float* b_c = (const float*)d_in[11];
    const float* U_o = (const float*)d_in[12];
    const float* V_o = (const float*)d_in[13];
    const float* b_o = (const float*)d_in[14];

    float* out    = (float*)d_out;
    float* out_hs = out;
    float* out_ht = out + (size_t)BATCH * SEQ * HID;
    float* out_ct = out_ht + (size_t)BATCH * HID;

    static_assert(SMEM_BYTES <= 232448, "smem budget (persist)");
    static_assert(XU_SMEM <= 101376, "smem budget (xu, 2/SM)");
    cudaFuncSetAttribute(lstm_persist,
                         cudaFuncAttributeMaxDynamicSharedMemorySize,
                         SMEM_BYTES);
    cudaFuncSetAttribute(xu_mma,
                         cudaFuncAttributeMaxDynamicSharedMemorySize,
                         XU_SMEM);

    size_t total4 = XN4 + 4 * UG4;
    cvt_split<<<(unsigned)(total4 / 256), 256>>>(x, h0, U_i, U_f, U_c, U_o);

    dim3 g1(128, 32);
    xu_mma<<<g1, 256, XU_SMEM>>>(b_i, b_f, b_c, b_o);

    lstm_persist<<<NCTA, NTH, SMEM_BYTES>>>(
        V_i, V_f, V_c, V_o, c0, out_hs, out_ht, out_ct);
}

// round 16
// speedup vs baseline: 1.1124x; 1.0256x over previous
#include <cuda_runtime.h>
#include <cuda_bf16.h>

#define BATCH 32
#define SEQ   512
#define DIM   1024
#define HID   1024
#define NCTA  128
#define NTH   256

typedef unsigned long long ull;

// ---------------- scratch (device globals; no cudaMalloc allowed) ----------
__device__ float g_xu[(size_t)SEQ * BATCH * 4 * HID];   // [s][b][gate][j]
__device__ unsigned g_flags[NCTA * 8];                  // 32B-strided step counters
__device__ __nv_bfloat16 g_xh[(size_t)16384 * 1024];    // x hi  [m][k]
__device__ __nv_bfloat16 g_xl[(size_t)16384 * 1024];    // x lo
__device__ __nv_bfloat16 g_uh[(size_t)4 * 1024 * 1024]; // U hi  [g][k][n]
__device__ __nv_bfloat16 g_ul[(size_t)4 * 1024 * 1024]; // U lo
__device__ __nv_bfloat16 g_hbh[2][BATCH * HID];         // h hi [par][m][k]
__device__ __nv_bfloat16 g_hbl[2][BATCH * HID];         // h lo [par][m][k]

__device__ __forceinline__ float sigmoidf_(float x) {
    return 1.0f / (1.0f + __expf(-x));
}

// ---------------- tensor-core / async helpers --------------------------------
__device__ __forceinline__ unsigned smem_u32(const void* p) {
    return (unsigned)__cvta_generic_to_shared(p);
}
__device__ __forceinline__ void ldm_x4(unsigned* r, unsigned addr) {
    asm volatile("ldmatrix.sync.aligned.m8n8.x4.shared.b16 {%0,%1,%2,%3}, [%4];"
                 : "=r"(r[0]), "=r"(r[1]), "=r"(r[2]), "=r"(r[3]) : "r"(addr));
}
__device__ __forceinline__ void ldm_x4t(unsigned* r, unsigned addr) {
    asm volatile("ldmatrix.sync.aligned.m8n8.x4.trans.shared.b16 {%0,%1,%2,%3}, [%4];"
                 : "=r"(r[0]), "=r"(r[1]), "=r"(r[2]), "=r"(r[3]) : "r"(addr));
}
__device__ __forceinline__ void mma_bf16(float* d, const unsigned* a, const unsigned* b) {
    asm volatile(
        "mma.sync.aligned.m16n8k16.row.col.f32.bf16.bf16.f32 "
        "{%0,%1,%2,%3}, {%4,%5,%6,%7}, {%8,%9}, {%0,%1,%2,%3};"
        : "+f"(d[0]), "+f"(d[1]), "+f"(d[2]), "+f"(d[3])
        : "r"(a[0]), "r"(a[1]), "r"(a[2]), "r"(a[3]), "r"(b[0]), "r"(b[1]));
}
__device__ __forceinline__ void cp16(unsigned saddr, const void* g) {
    asm volatile("cp.async.cg.shared.global [%0], [%1], 16;" :: "r"(saddr), "l"(g));
}
__device__ __forceinline__ void cp_commit() {
    asm volatile("cp.async.commit_group;");
}
template <int N> __device__ __forceinline__ void cp_wait() {
    asm volatile("cp.async.wait_group %0;" :: "n"(N));
}

// ---------------------------------------------------------------------------
// cvt_split: fp32 -> (bf16 hi, bf16 lo) for x and the 4 gate U matrices.
// Block 0 additionally seeds g_hbh/g_hbl[0] from h0 and zeroes the flags.
// ---------------------------------------------------------------------------
#define XN4 ((size_t)16384 * 1024 / 4)
#define UG4 ((size_t)1024 * 1024 / 4)
__global__ __launch_bounds__(256) void cvt_split(
    const float* __restrict__ x,  const float* __restrict__ h0,
    const float* __restrict__ Ui, const float* __restrict__ Uf,
    const float* __restrict__ Uc, const float* __restrict__ Uo)
{
    if (blockIdx.x == 0) {
        for (int idx = threadIdx.x; idx < BATCH * HID; idx += 256) {
            float v = h0[idx];
            __nv_bfloat16 hi = __float2bfloat16_rn(v);
            __nv_bfloat16 lo = __float2bfloat16_rn(v - __bfloat162float(hi));
            g_hbh[0][idx] = hi;
            g_hbl[0][idx] = lo;
        }
        for (int e = threadIdx.x; e < NCTA * 8; e += 256) g_flags[e] = 0;
    }

    size_t i4 = (size_t)blockIdx.x * 256 + threadIdx.x;
    const float4* src;
    __nv_bfloat162* dh;
    __nv_bfloat162* dl;
    size_t off;
    if (i4 < XN4) {
        src = (const float4*)x;   off = i4;
        dh = (__nv_bfloat162*)g_xh;
        dl = (__nv_bfloat162*)g_xl;
    } else {
        size_t j = i4 - XN4;
        int g = (int)(j >> 18);               // UG4 = 2^18
        size_t o = j & (UG4 - 1);
        const float* Ug = (g == 0) ? Ui : (g == 1) ? Uf : (g == 2) ? Uc : Uo;
        src = (const float4*)Ug;  off = o;
        dh = (__nv_bfloat162*)(g_uh + (size_t)g * 1024 * 1024);
        dl = (__nv_bfloat162*)(g_ul + (size_t)g * 1024 * 1024);
    }
    float4 v = src[off];
    __nv_bfloat16 h0v = __float2bfloat16_rn(v.x);
    __nv_bfloat16 h1 = __float2bfloat16_rn(v.y);
    __nv_bfloat16 h2 = __float2bfloat16_rn(v.z);
    __nv_bfloat16 h3 = __float2bfloat16_rn(v.w);
    __nv_bfloat16 l0 = __float2bfloat16_rn(v.x - __bfloat162float(h0v));
    __nv_bfloat16 l1 = __float2bfloat16_rn(v.y - __bfloat162float(h1));
    __nv_bfloat16 l2 = __float2bfloat16_rn(v.z - __bfloat162float(h2));
    __nv_bfloat16 l3 = __float2bfloat16_rn(v.w - __bfloat162float(h3));
    dh[off * 2]     = __halves2bfloat162(h0v, h1);
    dh[off * 2 + 1] = __halves2bfloat162(h2, h3);
    dl[off * 2]     = __halves2bfloat162(l0, l1);
    dl[off * 2 + 1] = __halves2bfloat162(l2, l3);
}

// ---------------------------------------------------------------------------
// Phase 1: g_xu = x @ U_g + b_g, split-bf16 mma.sync, 2-stage cp.async pipe.
// (unchanged R11 winner)
// ---------------------------------------------------------------------------
#define AS_STR 40
#define BS_STR 136
#define O_ASL  (128 * AS_STR)                 // 5120
#define O_BSH  (2 * 128 * AS_STR)             // 10240
#define O_BSL  (O_BSH + 32 * BS_STR)          // 14592
#define BUF_E  (O_BSL + 32 * BS_STR)          // 18944 bf16 elems / buffer
#define XU_SMEM (2 * BUF_E * 2)               // 75776 bytes

__global__ __launch_bounds__(256, 2) void xu_mma(
    const float* __restrict__ bi, const float* __restrict__ bf,
    const float* __restrict__ bc, const float* __restrict__ bo)
{
    extern __shared__ __nv_bfloat16 smb[];

    const int tid  = threadIdx.x;
    const int wid  = tid >> 5;
    const int lane = tid & 31;
    const int wm   = wid & 3;
    const int wn   = wid >> 2;
    const int m0   = blockIdx.x * 128;
    const int nb   = blockIdx.y;
    const int gate = nb >> 3;
    const int j0   = (nb & 7) * 128;

    const float* bias = (gate == 0) ? bi : (gate == 1) ? bf : (gate == 2) ? bc : bo;
    const __nv_bfloat16* __restrict__ Agh = g_xh;
    const __nv_bfloat16* __restrict__ Agl = g_xl;
    const __nv_bfloat16* __restrict__ Bgh = g_uh + (size_t)gate * 1024 * 1024;
    const __nv_bfloat16* __restrict__ Bgl = g_ul + (size_t)gate * 1024 * 1024;

    float acc[2][8][4];
    #pragma unroll
    for (int ti = 0; ti < 2; ti++)
        #pragma unroll
        for (int tj = 0; tj < 8; tj++)
            #pragma unroll
            for (int q = 0; q < 4; q++) acc[ti][tj][q] = 0.f;

    const int ar  = tid >> 2;
    const int ac  = tid & 3;
    const int br  = tid >> 4;
    const int bc2 = tid & 15;

    const int a_r = (lane & 15);
    const int a_c = (lane >> 4) << 3;
    const int b_k = (lane & 15);
    const int b_n = (lane >> 4) << 3;

    auto stage = [&](int b, int k0) {
        __nv_bfloat16* base = smb + b * BUF_E;
        #pragma unroll
        for (int u = 0; u < 2; ++u) {
            int row = ar + u * 64;
            cp16(smem_u32(&base[row * AS_STR + ac * 8]),
                 &Agh[(size_t)(m0 + row) * DIM + k0 + ac * 8]);
            cp16(smem_u32(&base[O_ASL + row * AS_STR + ac * 8]),
                 &Agl[(size_t)(m0 + row) * DIM + k0 + ac * 8]);
            int krow = br + u * 16;
            cp16(smem_u32(&base[O_BSH + krow * BS_STR + bc2 * 8]),
                 &Bgh[(size_t)(k0 + krow) * HID + j0 + bc2 * 8]);
            cp16(smem_u32(&base[O_BSL + krow * BS_STR + bc2 * 8]),
                 &Bgl[(size_t)(k0 + krow) * HID + j0 + bc2 * 8]);
        }
    };

    stage(0, 0);
    cp_commit();

    for (int c = 0; c < 32; ++c) {
        if (c < 31) {
            stage((c + 1) & 1, (c + 1) * 32);
            cp_commit();
            cp_wait<1>();
        } else {
            cp_wait<0>();
        }
        __syncthreads();

        const __nv_bfloat16* base = smb + (c & 1) * BUF_E;
        #pragma unroll
        for (int kk = 0; kk < 32; kk += 16) {
            unsigned Ah[2][4], Al[2][4], Bf[4][4];
            #pragma unroll
            for (int ti = 0; ti < 2; ++ti) {
                int row = wm * 32 + ti * 16 + a_r;
                ldm_x4(Ah[ti], smem_u32(&base[row * AS_STR + kk + a_c]));
                ldm_x4(Al[ti], smem_u32(&base[O_ASL + row * AS_STR + kk + a_c]));
            }
            #pragma unroll
            for (int p = 0; p < 4; ++p) {
                int n = wn * 64 + p * 16 + b_n;
                ldm_x4t(Bf[p], smem_u32(&base[O_BSH + (kk + b_k) * BS_STR + n]));
            }
            #pragma unroll
            for (int ti = 0; ti < 2; ++ti)
                #pragma unroll
                for (int p = 0; p < 4; ++p) {
                    mma_bf16(acc[ti][2 * p],     Ah[ti], &Bf[p][0]);
                    mma_bf16(acc[ti][2 * p + 1], Ah[ti], &Bf[p][2]);
                    mma_bf16(acc[ti][2 * p],     Al[ti], &Bf[p][0]);
                    mma_bf16(acc[ti][2 * p + 1], Al[ti], &Bf[p][2]);
                }
            #pragma unroll
            for (int p = 0; p < 4; ++p) {
                int n = wn * 64 + p * 16 + b_n;
                ldm_x4t(Bf[p], smem_u32(&base[O_BSL + (kk + b_k) * BS_STR + n]));
            }
            #pragma unroll
            for (int ti = 0; ti < 2; ++ti)
                #pragma unroll
                for (int p = 0; p < 4; ++p) {
                    mma_bf16(acc[ti][2 * p],     Ah[ti], &Bf[p][0]);
                    mma_bf16(acc[ti][2 * p + 1], Ah[ti], &Bf[p][2]);
                }
        }
        __syncthreads();
    }

    #pragma unroll
    for (int ti = 0; ti < 2; ++ti) {
        #pragma unroll
        for (int tj = 0; tj < 8; ++tj) {
            int col = j0 + wn * 64 + tj * 8 + (lane & 3) * 2;
            float c0 = __ldg(&bias[col]);
            float c1 = __ldg(&bias[col + 1]);
            int row0 = m0 + wm * 32 + ti * 16 + (lane >> 2);
            int row1 = row0 + 8;
            {
                int b_ = row0 >> 9, s_ = row0 & 511;
                float2* dst = (float2*)&g_xu[(((size_t)s_ * BATCH + b_) * 4 + gate) * HID + col];
                *dst = make_float2(acc[ti][tj][0] + c0, acc[ti][tj][1] + c1);
            }
            {
                int b_ = row1 >> 9, s_ = row1 & 511;
                float2* dst = (float2*)&g_xu[(((size_t)s_ * BATCH + b_) * 4 + gate) * HID + col];
                *dst = make_float2(acc[ti][tj][2] + c0, acc[ti][tj][3] + c1);
            }
        }
    }
}

// ---------------------------------------------------------------------------
// Phase 2: PERSISTENT recurrence — R11 skeleton with 2 CHUNKS of 512 k
// (the aligned version of R8's idea, never actually benched). Keeps: 8
// warps, single Hs buffer, strict store->sync->compute phases, upfront
// batched flag wait (2 flags/thread), flag post before output store.
// smem: V 163840 + Hs[32][520] hi+lo 66560 = 230400 B <= 232448.
// ---------------------------------------------------------------------------
#define VB_STR 40     // V smem row stride (bf16) — multiple of 8 (ldmatrix 16B)
#define KCH2   512    // h chunk k-size
#define HB_STR 520    // H smem row stride (bf16) = 512 + 8, multiple of 8
#define SC_WSTR (32 * 36)   // scratch floats per warp
#define SMEM_BYTES (2 * 1024 * VB_STR * 2 + 2 * 32 * HB_STR * 2)  // 230400

__global__ __launch_bounds__(NTH, 1) void lstm_persist(
    const float* __restrict__ Vi, const float* __restrict__ Vf,
    const float* __restrict__ Vc, const float* __restrict__ Vo,
    const float* __restrict__ c0,
    float* __restrict__ out_hs,
    float* __restrict__ out_ht,
    float* __restrict__ out_ct)
{
    extern __shared__ char smraw[];
    __nv_bfloat16* Vbh = (__nv_bfloat16*)smraw;            // [1024][VB_STR]
    __nv_bfloat16* Vbl = Vbh + 1024 * VB_STR;
    char* hregion = smraw + (size_t)2 * 1024 * VB_STR * 2;
    __nv_bfloat16* Hsh = (__nv_bfloat16*)hregion;          // [32][HB_STR]
    __nv_bfloat16* Hsl = Hsh + 32 * HB_STR;
    float* scr = (float*)hregion;                          // [8][32][36] alias

    const int tid  = threadIdx.x;
    const int wid  = tid >> 5;
    const int lane = tid & 31;
    const int jb   = blockIdx.x * 8;

    const int fm  = tid >> 3;            // gating: batch
    const int fj  = tid & 7;             // gating: local column
    const int fjg = jb + fj;

    const int a_r = (lane & 15);
    const int a_c = (lane >> 4) << 3;
    const int b_k = (lane & 15);
    const int b_n = (lane >> 4) << 3;

    // producer flags: staging slice kq (8 k wide) of chunk ch -> CTA ch*64+kq
    const int kq6 = tid & 63;
    const unsigned* fl0 = &g_flags[kq6 * 8];
    const unsigned* fl1 = &g_flags[(64 + kq6) * 8];

    // ---- one-time V load + split into smem ----
    for (int e = tid; e < 1024 * 32; e += NTH) {
        int k   = e >> 5;
        int col = e & 31;
        int j   = col >> 2;
        int g   = col & 3;
        const float* Vg = (g == 0) ? Vi : (g == 1) ? Vf : (g == 2) ? Vc : Vo;
        float v = __ldg(&Vg[(size_t)k * HID + jb + j]);
        __nv_bfloat16 hi = __float2bfloat16_rn(v);
        __nv_bfloat16 lo = __float2bfloat16_rn(v - __bfloat162float(hi));
        Vbh[k * VB_STR + col] = hi;
        Vbl[k * VB_STR + col] = lo;
    }
    float cc = __ldg(&c0[fm * HID + fjg]);
    __syncthreads();

    for (int s = 0; s < SEQ; ++s) {
        const __nv_bfloat16* __restrict__ hH = g_hbh[s & 1];
        const __nv_bfloat16* __restrict__ hL = g_hbl[s & 1];

        const float* xup = &g_xu[(((size_t)s * BATCH + fm) * 4) * HID + fjg];
        float xi = __ldcs(xup);
        float xf = __ldcs(xup + HID);
        float xg = __ldcs(xup + 2 * HID);
        float xo = __ldcs(xup + 3 * HID);

        // ---- distributed wait: this thread's 2 producers, batched ----
        {
            unsigned tgt = (unsigned)s;
            unsigned v0, v1;
            do {
                asm volatile("ld.acquire.gpu.global.u32 %0, [%1];" : "=r"(v0) : "l"(fl0));
                asm volatile("ld.acquire.gpu.global.u32 %0, [%1];" : "=r"(v1) : "l"(fl1));
            } while (v0 < tgt || v1 < tgt);
        }

        float acc[2][4][4];
        #pragma unroll
        for (int ti = 0; ti < 2; ti++)
            #pragma unroll
            for (int nj = 0; nj < 4; nj++)
                #pragma unroll
                for (int q = 0; q < 4; q++) acc[ti][nj][q] = 0.f;

        // prefetch chunk 0: [32 m][512 k] hi+lo (uint4 = 8 bf16)
        uint4 hrH[8], hrL[8];
        #pragma unroll
        for (int r = 0; r < 8; ++r) {
            int idx = r * 256 + tid;      // 0..2047
            int m   = idx >> 6;
            int kq  = idx & 63;
            hrH[r] = __ldcg((const uint4*)&hH[m * HID + kq * 8]);
            hrL[r] = __ldcg((const uint4*)&hL[m * HID + kq * 8]);
        }

        #pragma unroll
        for (int ch = 0; ch < 2; ++ch) {
            __syncthreads();              // previous chunk compute / scratch done
            #pragma unroll
            for (int r = 0; r < 8; ++r) {
                int idx = r * 256 + tid;
                int m   = idx >> 6;
                int kq  = idx & 63;
                *(uint4*)&Hsh[m * HB_STR + kq * 8] = hrH[r];
                *(uint4*)&Hsl[m * HB_STR + kq * 8] = hrL[r];
            }
            __syncthreads();
            if (ch == 0) {                // prefetch chunk 1 (overlaps compute)
                #pragma unroll
                for (int r = 0; r < 8; ++r) {
                    int idx = r * 256 + tid;
                    int m   = idx >> 6;
                    int kq  = idx & 63;
                    hrH[r] = __ldcg((const uint4*)&hH[m * HID + KCH2 + kq * 8]);
                    hrL[r] = __ldcg((const uint4*)&hL[m * HID + KCH2 + kq * 8]);
                }
            }

            // warp's k-slice within chunk: [wid*64, wid*64+64)
            #pragma unroll
            for (int kk = 0; kk < 64; kk += 16) {
                int kloc = wid * 64 + kk;             // k within chunk
                int kglb = ch * KCH2 + kloc;          // k within 1024 (for V)
                unsigned Ah[2][4], Al[2][4], Bh[2][4], Bl[2][4];
                #pragma unroll
                for (int ti = 0; ti < 2; ++ti) {
                    int row = ti * 16 + a_r;
                    ldm_x4(Ah[ti], smem_u32(&Hsh[row * HB_STR + kloc + a_c]));
                    ldm_x4(Al[ti], smem_u32(&Hsl[row * HB_STR + kloc + a_c]));
                }
                #pragma unroll
                for (int q = 0; q < 2; ++q) {
                    int n = q * 16 + b_n;
                    ldm_x4t(Bh[q], smem_u32(&Vbh[(kglb + b_k) * VB_STR + n]));
                    ldm_x4t(Bl[q], smem_u32(&Vbl[(kglb + b_k) * VB_STR + n]));
                }
                #pragma unroll
                for (int ti = 0; ti < 2; ++ti)
                    #pragma unroll
                    for (int q = 0; q < 2; ++q) {
                        mma_bf16(acc[ti][2 * q],     Ah[ti], &Bh[q][0]);
                        mma_bf16(acc[ti][2 * q + 1], Ah[ti], &Bh[q][2]);
                        mma_bf16(acc[ti][2 * q],     Al[ti], &Bh[q][0]);
                        mma_bf16(acc[ti][2 * q + 1], Al[ti], &Bh[q][2]);
                        mma_bf16(acc[ti][2 * q],     Ah[ti], &Bl[q][0]);
                        mma_bf16(acc[ti][2 * q + 1], Ah[ti], &Bl[q][2]);
                    }
            }
        }

        // ---- cross-warp reduction via scratch (aliases H region) ----
        __syncthreads();
        #pragma unroll
        for (int ti = 0; ti < 2; ++ti)
            #pragma unroll
            for (int nj = 0; nj < 4; ++nj)
                #pragma unroll
                for (int u = 0; u < 2; ++u) {
                    int row = ti * 16 + (lane >> 2) + u * 8;
                    int col = nj * 8 + (lane & 3) * 2;
                    *(float2*)&scr[wid * SC_WSTR + row * 36 + col] =
                        make_float2(acc[ti][nj][2 * u], acc[ti][nj][2 * u + 1]);
                }
        __syncthreads();

        float zi = xi, zf = xf, zg = xg, zo = xo;
        #pragma unroll
        for (int w8 = 0; w8 < 8; ++w8) {
            float4 p = *(const float4*)&scr[w8 * SC_WSTR + fm * 36 + fj * 4];
            zi += p.x; zf += p.y; zg += p.z; zo += p.w;
        }

        float ig = sigmoidf_(zi);
        float fg = sigmoidf_(zf);
        float gg = tanhf(zg);
        float og = sigmoidf_(zo);
        cc = fg * cc + ig * gg;
        float h = og * tanhf(cc);

        __nv_bfloat16 hhi = __float2bfloat16_rn(h);
        __nv_bfloat16 hlo = __float2bfloat16_rn(h - __bfloat162float(hhi));
        g_hbh[(s + 1) & 1][fm * HID + fjg] = hhi;
        g_hbl[(s + 1) & 1][fm * HID + fjg] = hlo;

        __syncthreads();                  // all h stores issued (CTA-wide)
        if (tid == 0) {
            asm volatile("st.release.gpu.global.u32 [%0], %1;"
                         :: "l"(&g_flags[blockIdx.x * 8]), "r"((unsigned)(s + 1))
                         : "memory");
        }

        // streaming output store AFTER the flag post (off the critical path)
        __stcs(&out_hs[((size_t)fm * SEQ + s) * HID + fjg], h);

        if (s == SEQ - 1) {
            out_ht[fm * HID + fjg] = h;
            out_ct[fm * HID + fjg] = cc;
        }
    }
}

// ---------------------------------------------------------------------------
extern "C" void kernel_launch(void* const* d_in, const int* in_sizes, int n_in,
                              void* d_out, int out_size) {
    const float* x   = (const float*)d_in[0];
    const float* h0  = (const float*)d_in[1];
    const float* c0  = (const float*)d_in[2];
    const float* U_i = (const float*)d_in[3];
    const float* V_i = (const float*)d_in[4];
    const float* b_i = (const float*)d_in[5];
    const float* U_f = (const float*)d_in[6];
    const float* V_f = (const float*)d_in[7];
    const float* b_f = (const float*)d_in[8];
    const float* U_c = (const float*)d_in[9];
    const float* V_c = (const float*)d_in[10];
    const float* b_c = (const float*)d_in[11];
    const float* U_o = (const float*)d_in[12];
    const float* V_o = (const float*)d_in[13];
    const float* b_o = (const float*)d_in[14];

    float* out    = (float*)d_out;
    float* out_hs = out;
    float* out_ht = out + (size_t)BATCH * SEQ * HID;
    float* out_ct = out_ht + (size_t)BATCH * HID;

    static_assert(SMEM_BYTES <= 232448, "smem budget (persist)");
    static_assert(XU_SMEM <= 101376, "smem budget (xu, 2/SM)");
    cudaFuncSetAttribute(lstm_persist,
                         cudaFuncAttributeMaxDynamicSharedMemorySize,
                         SMEM_BYTES);
    cudaFuncSetAttribute(xu_mma,
                         cudaFuncAttributeMaxDynamicSharedMemorySize,
                         XU_SMEM);

    size_t total4 = XN4 + 4 * UG4;
    cvt_split<<<(unsigned)(total4 / 256), 256>>>(x, h0, U_i, U_f, U_c, U_o);

    dim3 g1(128, 32);
    xu_mma<<<g1, 256, XU_SMEM>>>(b_i, b_f, b_c, b_o);

    lstm_persist<<<NCTA, NTH, SMEM_BYTES>>>(
        V_i, V_f, V_c, V_o, c0, out_hs, out_ht, out_ct);
}